// round 10
// baseline (speedup 1.0000x reference)
#include <cuda_runtime.h>
#include <cstdint>

#define NF       40960
#define MDIM     256
#define NB       2048
#define ROWS     (2*NB)          // 4096 feature rows (white then black)
#define WPR      1280            // bitmap words per row (NF/32)
#define CHUNK_V4 1280            // float4s per warp chunk (NF/4/8)
#define CAP      192             // per-color index list capacity

#define SCAN_CTAS 4096           // 8 warps per CTA, warp per (row, eighth)
#define TR_X      (NF/32)        // 1280
#define TR_Y      (MDIM/32)      // 8
#define TR_CTAS   (TR_X*TR_Y)    // 10240

// Transposed feature-transformer weights: ft_wT[f][m], 40960 x 256 fp32 = 41.9 MB
__device__ float g_ftwT[NF * MDIM];
// Nonzero bitmap: 4096 rows x 1280 words = 20 MB
__device__ unsigned g_bitmap[ROWS * WPR];

// ---------------------------------------------------------------------------
// Kernel 1: fused [streaming scan -> bitmap] + [ft_w transpose].
// (unchanged — ~107us, near the stream floor)
// ---------------------------------------------------------------------------
__global__ __launch_bounds__(256) void scan_transpose_kernel(
    const float* __restrict__ wf,
    const float* __restrict__ bfeat,
    const float* __restrict__ ft_w)
{
    __shared__ float tile[32][33];

    if (blockIdx.x < SCAN_CTAS) {
        const int gw     = (blockIdx.x << 3) | (threadIdx.x >> 5);
        const int lane   = threadIdx.x & 31;
        const int row    = gw >> 3;
        const int eighth = gw & 7;

        const float* rowp = (row < NB) ? (wf + (size_t)row * NF)
                                       : (bfeat + (size_t)(row - NB) * NF);
        const uint4* p = reinterpret_cast<const uint4*>(rowp) + eighth * CHUNK_V4;
        unsigned* wout = g_bitmap + (size_t)row * WPR + eighth * 160;

        #pragma unroll
        for (int t = 0; t < 5; t++) {
            unsigned mask = 0u;
            #pragma unroll
            for (int g = 0; g < 2; g++) {
                uint4 v0 = __ldcs(&p[t * 256 + (g * 4 + 0) * 32 + lane]);
                uint4 v1 = __ldcs(&p[t * 256 + (g * 4 + 1) * 32 + lane]);
                uint4 v2 = __ldcs(&p[t * 256 + (g * 4 + 2) * 32 + lane]);
                uint4 v3 = __ldcs(&p[t * 256 + (g * 4 + 3) * 32 + lane]);
                const int s = g * 16;
                if (v0.x) mask |= 1u << (s + 0);  if (v0.y) mask |= 1u << (s + 1);
                if (v0.z) mask |= 1u << (s + 2);  if (v0.w) mask |= 1u << (s + 3);
                if (v1.x) mask |= 1u << (s + 4);  if (v1.y) mask |= 1u << (s + 5);
                if (v1.z) mask |= 1u << (s + 6);  if (v1.w) mask |= 1u << (s + 7);
                if (v2.x) mask |= 1u << (s + 8);  if (v2.y) mask |= 1u << (s + 9);
                if (v2.z) mask |= 1u << (s + 10); if (v2.w) mask |= 1u << (s + 11);
                if (v3.x) mask |= 1u << (s + 12); if (v3.y) mask |= 1u << (s + 13);
                if (v3.z) mask |= 1u << (s + 14); if (v3.w) mask |= 1u << (s + 15);
            }
            wout[t * 32 + lane] = mask;
        }
    } else {
        const int tb = blockIdx.x - SCAN_CTAS;
        const int f0 = (tb % TR_X) * 32;
        const int m0 = (tb / TR_X) * 32;
        const int t  = threadIdx.x;
        {
            const int m = t >> 3;
            const int q = t & 7;
            const float4 v = *reinterpret_cast<const float4*>(
                ft_w + (size_t)(m0 + m) * NF + f0 + q * 4);
            tile[m][q * 4 + 0] = v.x;
            tile[m][q * 4 + 1] = v.y;
            tile[m][q * 4 + 2] = v.z;
            tile[m][q * 4 + 3] = v.w;
        }
        __syncthreads();
        {
            const int f  = t >> 3;
            const int m4 = t & 7;
            float4 v;
            v.x = tile[m4 * 4 + 0][f];
            v.y = tile[m4 * 4 + 1][f];
            v.z = tile[m4 * 4 + 2][f];
            v.w = tile[m4 * 4 + 3][f];
            *reinterpret_cast<float4*>(
                g_ftwT + (size_t)(f0 + f) * MDIM + m0 + m4 * 4) = v;
        }
    }
}

// ---------------------------------------------------------------------------
// Kernel 2: bitmap decode + gather + MLP tail. 512 threads per position:
// gather chain split across 2 thread-halves (fixed combine order).
// ---------------------------------------------------------------------------
__device__ __forceinline__ float clamp01(float x) {
    return fminf(fmaxf(x, 0.0f), 1.0f);
}

__device__ __forceinline__ int decode_f(int w, int j) {
    const int eighth = w / 160;
    const int r      = w - eighth * 160;
    const int t      = r >> 5;
    const int l      = r & 31;
    return eighth * 5120 + t * 1024 + (j >> 2) * 128 + l * 4 + (j & 3);
}

__global__ __launch_bounds__(512) void gather_mlp_kernel(
    const float* __restrict__ stm,
    const float* __restrict__ ft_b,
    const float* __restrict__ l1_w,
    const float* __restrict__ l1_b,
    const float* __restrict__ l2_w,
    const float* __restrict__ l2_b,
    const float* __restrict__ l3_w,
    const float* __restrict__ l3_b,
    float* __restrict__ out)
{
    const int b    = blockIdx.x;
    const int tid  = threadIdx.x;          // 0..511
    const int lane = tid & 31;
    const int wid  = tid >> 5;             // 0..15
    const int m    = tid & 255;            // output unit
    const int half = tid >> 8;             // gather half

    __shared__ __align__(16) float s_h[512];
    __shared__ __align__(16) int   s_idxW[CAP];
    __shared__ __align__(16) int   s_idxB[CAP];
    __shared__ float s_pW[2][256];         // per-half gather partials
    __shared__ float s_pB[2][256];
    __shared__ float s_l2w[32 * 33];
    __shared__ float s_l2x[32];
    __shared__ int   s_wsum[8], s_bsum[8];
    __shared__ int   s_nW, s_nB;

    // threads 256-511: stage l2_w into padded smem (concurrent with decode)
    if (tid >= 256) {
        for (int i = tid - 256; i < 1024; i += 256)
            s_l2w[(i >> 5) * 33 + (i & 31)] = l2_w[i];
    }

    // ---- decode on threads 0..255: words w = k*256 + tid, k = 0..4 ----
    unsigned ww[5], bw[5];
    int cw = 0, cb = 0, wexc = 0, bexc = 0;
    if (tid < 256) {
        const unsigned* wbm = g_bitmap + (size_t)b * WPR;
        const unsigned* bbm = g_bitmap + (size_t)(NB + b) * WPR;
        #pragma unroll
        for (int k = 0; k < 5; k++) {
            ww[k] = __ldcs(&wbm[k * 256 + tid]);
            bw[k] = __ldcs(&bbm[k * 256 + tid]);
        }
        #pragma unroll
        for (int k = 0; k < 5; k++) {
            cw += __popc(ww[k]);
            cb += __popc(bw[k]);
        }
        // warp-level exclusive prefix sums (deterministic thread order)
        wexc = cw; bexc = cb;
        #pragma unroll
        for (int d = 1; d < 32; d <<= 1) {
            const int nw = __shfl_up_sync(0xffffffffu, wexc, d);
            const int nb = __shfl_up_sync(0xffffffffu, bexc, d);
            if (lane >= d) { wexc += nw; bexc += nb; }
        }
        wexc -= cw; bexc -= cb;
        if (lane == 31) {
            s_wsum[wid] = wexc + cw;
            s_bsum[wid] = bexc + cb;
        }
    }
    __syncthreads();
    if (tid == 0) {
        int aw = 0, ab = 0;
        #pragma unroll
        for (int i = 0; i < 8; i++) {
            const int tw = s_wsum[i]; s_wsum[i] = aw; aw += tw;
            const int tb = s_bsum[i]; s_bsum[i] = ab; ab += tb;
        }
        s_nW = (aw < CAP) ? aw : CAP;
        s_nB = (ab < CAP) ? ab : CAP;
    }
    __syncthreads();

    // deposit indices in deterministic (thread, word, bit) order
    if (tid < 256) {
        int ow = s_wsum[wid] + wexc;
        int ob = s_bsum[wid] + bexc;
        #pragma unroll
        for (int k = 0; k < 5; k++) {
            unsigned mm = ww[k];
            const int w = k * 256 + tid;
            while (mm) {
                const int j = __ffs(mm) - 1;
                mm &= mm - 1u;
                if (ow < CAP) s_idxW[ow] = decode_f(w, j);
                ow++;
            }
            mm = bw[k];
            while (mm) {
                const int j = __ffs(mm) - 1;
                mm &= mm - 1u;
                if (ob < CAP) s_idxB[ob] = decode_f(w, j);
                ob++;
            }
        }
    }
    __syncthreads();

    // ---- gather: half h of the lists, all 512 threads ----
    {
        const int nW = s_nW;
        const int hW = nW >> 1;
        const int jbW = half ? hW : 0;
        const int jeW = half ? nW : hW;
        float acc = 0.0f;
        int j = jbW;
        for (; j + 8 <= jeW; j += 8) {
            float a0 = g_ftwT[(size_t)s_idxW[j + 0] * MDIM + m];
            float a1 = g_ftwT[(size_t)s_idxW[j + 1] * MDIM + m];
            float a2 = g_ftwT[(size_t)s_idxW[j + 2] * MDIM + m];
            float a3 = g_ftwT[(size_t)s_idxW[j + 3] * MDIM + m];
            float a4 = g_ftwT[(size_t)s_idxW[j + 4] * MDIM + m];
            float a5 = g_ftwT[(size_t)s_idxW[j + 5] * MDIM + m];
            float a6 = g_ftwT[(size_t)s_idxW[j + 6] * MDIM + m];
            float a7 = g_ftwT[(size_t)s_idxW[j + 7] * MDIM + m];
            acc += a0; acc += a1; acc += a2; acc += a3;
            acc += a4; acc += a5; acc += a6; acc += a7;
        }
        for (; j < jeW; j++) acc += g_ftwT[(size_t)s_idxW[j] * MDIM + m];
        s_pW[half][m] = acc;

        const int nB = s_nB;
        const int hB = nB >> 1;
        const int jbB = half ? hB : 0;
        const int jeB = half ? nB : hB;
        acc = 0.0f;
        j = jbB;
        for (; j + 8 <= jeB; j += 8) {
            float a0 = g_ftwT[(size_t)s_idxB[j + 0] * MDIM + m];
            float a1 = g_ftwT[(size_t)s_idxB[j + 1] * MDIM + m];
            float a2 = g_ftwT[(size_t)s_idxB[j + 2] * MDIM + m];
            float a3 = g_ftwT[(size_t)s_idxB[j + 3] * MDIM + m];
            float a4 = g_ftwT[(size_t)s_idxB[j + 4] * MDIM + m];
            float a5 = g_ftwT[(size_t)s_idxB[j + 5] * MDIM + m];
            float a6 = g_ftwT[(size_t)s_idxB[j + 6] * MDIM + m];
            float a7 = g_ftwT[(size_t)s_idxB[j + 7] * MDIM + m];
            acc += a0; acc += a1; acc += a2; acc += a3;
            acc += a4; acc += a5; acc += a6; acc += a7;
        }
        for (; j < jeB; j++) acc += g_ftwT[(size_t)s_idxB[j] * MDIM + m];
        s_pB[half][m] = acc;
    }
    __syncthreads();

    // ---- combine halves (fixed order) + stm blend + clip ----
    if (tid < 256) {
        const float bias = ft_b[m];
        const float accW = bias + s_pW[0][m] + s_pW[1][m];
        const float accB = bias + s_pB[0][m] + s_pB[1][m];
        const float s = stm[b];
        s_h[m]       = clamp01(s * accW + (1.0f - s) * accB);
        s_h[256 + m] = clamp01(s * accB + (1.0f - s) * accW);
    }
    __syncthreads();

    // L1: 512 -> 32, warp-per-output (2 outputs per warp, 16 warps).
    {
        const float4* hv = reinterpret_cast<const float4*>(s_h);
        #pragma unroll
        for (int r = 0; r < 2; r++) {
            const int n = wid * 2 + r;
            const float4* wr = reinterpret_cast<const float4*>(l1_w + n * 512);
            float p = 0.0f;
            #pragma unroll
            for (int i = 0; i < 4; i++) {
                const float4 a = wr[i * 32 + lane];
                const float4 x = hv[i * 32 + lane];
                p += a.x * x.x;
                p += a.y * x.y;
                p += a.z * x.z;
                p += a.w * x.w;
            }
            p += __shfl_down_sync(0xffffffffu, p, 16);
            p += __shfl_down_sync(0xffffffffu, p, 8);
            p += __shfl_down_sync(0xffffffffu, p, 4);
            p += __shfl_down_sync(0xffffffffu, p, 2);
            p += __shfl_down_sync(0xffffffffu, p, 1);
            if (lane == 0) s_l2x[n] = clamp01(p + l1_b[n]);
        }
    }
    __syncthreads();

    // L2 (32->32) from padded smem, L3 (32->1). Warp 0 only.
    if (tid < 32) {
        float q = l2_b[tid];
        #pragma unroll
        for (int k = 0; k < 32; k++) q += s_l2w[tid * 33 + k] * s_l2x[k];
        const float l3x = clamp01(q);
        float t = l3x * l3_w[tid];
        #pragma unroll
        for (int off = 16; off > 0; off >>= 1)
            t += __shfl_down_sync(0xffffffffu, t, off);
        if (tid == 0) {
            const float ev = clamp01(t + l3_b[0]);
            out[b] = (ev - 0.5f) * 2.0f * 10000.0f;
        }
    }
}

// ---------------------------------------------------------------------------
// Launch
// ---------------------------------------------------------------------------
extern "C" void kernel_launch(void* const* d_in, const int* in_sizes, int n_in,
                              void* d_out, int out_size)
{
    const float* wf    = (const float*)d_in[0];
    const float* bfeat = (const float*)d_in[1];
    const float* stm   = (const float*)d_in[2];
    const float* ft_w  = (const float*)d_in[3];
    const float* ft_b  = (const float*)d_in[4];
    const float* l1_w  = (const float*)d_in[5];
    const float* l1_b  = (const float*)d_in[6];
    const float* l2_w  = (const float*)d_in[7];
    const float* l2_b  = (const float*)d_in[8];
    const float* l3_w  = (const float*)d_in[9];
    const float* l3_b  = (const float*)d_in[10];
    float* out = (float*)d_out;

    // 1) Fused scan (bitmap) + transpose in one grid
    scan_transpose_kernel<<<SCAN_CTAS + TR_CTAS, 256>>>(wf, bfeat, ft_w);

    // 2) Decode + gather + MLP tail, 512 threads per position
    gather_mlp_kernel<<<NB, 512>>>(stm, ft_b, l1_w, l1_b, l2_w, l2_b,
                                   l3_w, l3_b, out);
}

// round 12
// speedup vs baseline: 1.1031x; 1.1031x over previous
#include <cuda_runtime.h>
#include <cstdint>

#define NF       40960
#define MDIM     256
#define NB       2048
#define ROWS     (2*NB)          // 4096 feature rows (white then black)
#define WPR      1280            // bitmap words per row (NF/32)
#define CHUNK_V4 1280            // float4s per warp chunk (NF/4/8)
#define CAP      192             // per-color index list capacity

#define SCAN_CTAS 4096           // 8 warps per CTA, warp per (row, eighth)
#define TR_X      (NF/32)        // 1280
#define TR_Y      (MDIM/32)      // 8
#define TR_CTAS   (TR_X*TR_Y)    // 10240

// Transposed feature-transformer weights: ft_wT[f][m], 40960 x 256 fp32 = 41.9 MB
__device__ float g_ftwT[NF * MDIM];
// Nonzero bitmap: 4096 rows x 1280 words = 20 MB
__device__ unsigned g_bitmap[ROWS * WPR];

// ---------------------------------------------------------------------------
// Kernel 1: fused [streaming scan -> bitmap] + [ft_w transpose].
// (unchanged — ~107us, near the stream floor)
// ---------------------------------------------------------------------------
__global__ __launch_bounds__(256) void scan_transpose_kernel(
    const float* __restrict__ wf,
    const float* __restrict__ bfeat,
    const float* __restrict__ ft_w)
{
    __shared__ float tile[32][33];

    if (blockIdx.x < SCAN_CTAS) {
        const int gw     = (blockIdx.x << 3) | (threadIdx.x >> 5);
        const int lane   = threadIdx.x & 31;
        const int row    = gw >> 3;
        const int eighth = gw & 7;

        const float* rowp = (row < NB) ? (wf + (size_t)row * NF)
                                       : (bfeat + (size_t)(row - NB) * NF);
        const uint4* p = reinterpret_cast<const uint4*>(rowp) + eighth * CHUNK_V4;
        unsigned* wout = g_bitmap + (size_t)row * WPR + eighth * 160;

        #pragma unroll
        for (int t = 0; t < 5; t++) {
            unsigned mask = 0u;
            #pragma unroll
            for (int g = 0; g < 2; g++) {
                uint4 v0 = __ldcs(&p[t * 256 + (g * 4 + 0) * 32 + lane]);
                uint4 v1 = __ldcs(&p[t * 256 + (g * 4 + 1) * 32 + lane]);
                uint4 v2 = __ldcs(&p[t * 256 + (g * 4 + 2) * 32 + lane]);
                uint4 v3 = __ldcs(&p[t * 256 + (g * 4 + 3) * 32 + lane]);
                const int s = g * 16;
                if (v0.x) mask |= 1u << (s + 0);  if (v0.y) mask |= 1u << (s + 1);
                if (v0.z) mask |= 1u << (s + 2);  if (v0.w) mask |= 1u << (s + 3);
                if (v1.x) mask |= 1u << (s + 4);  if (v1.y) mask |= 1u << (s + 5);
                if (v1.z) mask |= 1u << (s + 6);  if (v1.w) mask |= 1u << (s + 7);
                if (v2.x) mask |= 1u << (s + 8);  if (v2.y) mask |= 1u << (s + 9);
                if (v2.z) mask |= 1u << (s + 10); if (v2.w) mask |= 1u << (s + 11);
                if (v3.x) mask |= 1u << (s + 12); if (v3.y) mask |= 1u << (s + 13);
                if (v3.z) mask |= 1u << (s + 14); if (v3.w) mask |= 1u << (s + 15);
            }
            wout[t * 32 + lane] = mask;
        }
    } else {
        const int tb = blockIdx.x - SCAN_CTAS;
        const int f0 = (tb % TR_X) * 32;
        const int m0 = (tb / TR_X) * 32;
        const int t  = threadIdx.x;
        {
            const int m = t >> 3;
            const int q = t & 7;
            const float4 v = *reinterpret_cast<const float4*>(
                ft_w + (size_t)(m0 + m) * NF + f0 + q * 4);
            tile[m][q * 4 + 0] = v.x;
            tile[m][q * 4 + 1] = v.y;
            tile[m][q * 4 + 2] = v.z;
            tile[m][q * 4 + 3] = v.w;
        }
        __syncthreads();
        {
            const int f  = t >> 3;
            const int m4 = t & 7;
            float4 v;
            v.x = tile[m4 * 4 + 0][f];
            v.y = tile[m4 * 4 + 1][f];
            v.z = tile[m4 * 4 + 2][f];
            v.w = tile[m4 * 4 + 3][f];
            *reinterpret_cast<float4*>(
                g_ftwT + (size_t)(f0 + f) * MDIM + m0 + m4 * 4) = v;
        }
    }
}

// ---------------------------------------------------------------------------
// Kernel 2: bitmap decode + float4 gather + MLP tail. 256 threads/position.
// Gather: thread = (grp = tid>>6, m4 = tid&63). Each thread LDG.128s its
// float4 of 4 m-values over its quarter of the index list. Quarter partials
// combine via smem in fixed g-order (deterministic).
// ---------------------------------------------------------------------------
__device__ __forceinline__ float clamp01(float x) {
    return fminf(fmaxf(x, 0.0f), 1.0f);
}

__device__ __forceinline__ int decode_f(int w, int j) {
    const int eighth = w / 160;
    const int r      = w - eighth * 160;
    const int t      = r >> 5;
    const int l      = r & 31;
    return eighth * 5120 + t * 1024 + (j >> 2) * 128 + l * 4 + (j & 3);
}

__device__ __forceinline__ float4 ld_row4(int f, int m4) {
    return reinterpret_cast<const float4*>(g_ftwT + (size_t)f * MDIM)[m4];
}

__global__ __launch_bounds__(256) void gather_mlp_kernel(
    const float* __restrict__ stm,
    const float* __restrict__ ft_b,
    const float* __restrict__ l1_w,
    const float* __restrict__ l1_b,
    const float* __restrict__ l2_w,
    const float* __restrict__ l2_b,
    const float* __restrict__ l3_w,
    const float* __restrict__ l3_b,
    float* __restrict__ out)
{
    const int b    = blockIdx.x;
    const int tid  = threadIdx.x;
    const int lane = tid & 31;
    const int wid  = tid >> 5;
    const int m4   = tid & 63;     // float4 column group (m = m4*4..m4*4+3)
    const int grp  = tid >> 6;     // quarter of the index list

    __shared__ __align__(16) float s_h[512];
    __shared__ __align__(16) float s_pW[4 * 256];  // [g][m] quarter partials
    __shared__ __align__(16) float s_pB[4 * 256];
    __shared__ __align__(16) int   s_idxW[CAP];
    __shared__ __align__(16) int   s_idxB[CAP];
    __shared__ float s_l2w[32 * 33];
    __shared__ float s_l2x[32];
    __shared__ int   s_wsum[8], s_bsum[8];
    __shared__ int   s_nW, s_nB;

    // stage l2_w into padded smem (coalesced; overlaps with bitmap latency)
    #pragma unroll
    for (int i = tid; i < 1024; i += 256)
        s_l2w[(i >> 5) * 33 + (i & 31)] = l2_w[i];

    // ---- decode: thread tid owns bitmap words w = k*256 + tid, k = 0..4 ----
    unsigned ww[5], bw[5];
    const unsigned* wbm = g_bitmap + (size_t)b * WPR;
    const unsigned* bbm = g_bitmap + (size_t)(NB + b) * WPR;
    #pragma unroll
    for (int k = 0; k < 5; k++) {
        ww[k] = __ldcs(&wbm[k * 256 + tid]);
        bw[k] = __ldcs(&bbm[k * 256 + tid]);
    }

    int cw = 0, cb = 0;
    #pragma unroll
    for (int k = 0; k < 5; k++) {
        cw += __popc(ww[k]);
        cb += __popc(bw[k]);
    }

    // CTA exclusive prefix sums (deterministic thread order)
    int wexc = cw, bexc = cb;
    #pragma unroll
    for (int d = 1; d < 32; d <<= 1) {
        const int nw = __shfl_up_sync(0xffffffffu, wexc, d);
        const int nb = __shfl_up_sync(0xffffffffu, bexc, d);
        if (lane >= d) { wexc += nw; bexc += nb; }
    }
    wexc -= cw; bexc -= cb;
    if (lane == 31) {
        s_wsum[wid] = wexc + cw;
        s_bsum[wid] = bexc + cb;
    }
    __syncthreads();
    if (tid == 0) {
        int aw = 0, ab = 0;
        #pragma unroll
        for (int i = 0; i < 8; i++) {
            const int tw = s_wsum[i]; s_wsum[i] = aw; aw += tw;
            const int tb = s_bsum[i]; s_bsum[i] = ab; ab += tb;
        }
        s_nW = (aw < CAP) ? aw : CAP;
        s_nB = (ab < CAP) ? ab : CAP;
    }
    __syncthreads();

    // deposit indices in deterministic (thread, word, bit) order
    {
        int ow = s_wsum[wid] + wexc;
        int ob = s_bsum[wid] + bexc;
        #pragma unroll
        for (int k = 0; k < 5; k++) {
            unsigned mm = ww[k];
            const int w = k * 256 + tid;
            while (mm) {
                const int j = __ffs(mm) - 1;
                mm &= mm - 1u;
                if (ow < CAP) s_idxW[ow] = decode_f(w, j);
                ow++;
            }
            mm = bw[k];
            while (mm) {
                const int j = __ffs(mm) - 1;
                mm &= mm - 1u;
                if (ob < CAP) s_idxB[ob] = decode_f(w, j);
                ob++;
            }
        }
    }
    __syncthreads();

    // ---- float4 gather over this thread's quarter of each list ----
    {
        const int nW = s_nW;
        const int j0 = (nW * grp) >> 2;
        const int j1 = (nW * (grp + 1)) >> 2;
        float4 acc = make_float4(0.f, 0.f, 0.f, 0.f);
        int j = j0;
        for (; j + 4 <= j1; j += 4) {
            const float4 v0 = ld_row4(s_idxW[j + 0], m4);
            const float4 v1 = ld_row4(s_idxW[j + 1], m4);
            const float4 v2 = ld_row4(s_idxW[j + 2], m4);
            const float4 v3 = ld_row4(s_idxW[j + 3], m4);
            acc.x += v0.x; acc.y += v0.y; acc.z += v0.z; acc.w += v0.w;
            acc.x += v1.x; acc.y += v1.y; acc.z += v1.z; acc.w += v1.w;
            acc.x += v2.x; acc.y += v2.y; acc.z += v2.z; acc.w += v2.w;
            acc.x += v3.x; acc.y += v3.y; acc.z += v3.z; acc.w += v3.w;
        }
        for (; j < j1; j++) {
            const float4 v = ld_row4(s_idxW[j], m4);
            acc.x += v.x; acc.y += v.y; acc.z += v.z; acc.w += v.w;
        }
        reinterpret_cast<float4*>(&s_pW[grp * 256])[m4] = acc;

        const int nB = s_nB;
        const int k0 = (nB * grp) >> 2;
        const int k1 = (nB * (grp + 1)) >> 2;
        acc = make_float4(0.f, 0.f, 0.f, 0.f);
        j = k0;
        for (; j + 4 <= k1; j += 4) {
            const float4 v0 = ld_row4(s_idxB[j + 0], m4);
            const float4 v1 = ld_row4(s_idxB[j + 1], m4);
            const float4 v2 = ld_row4(s_idxB[j + 2], m4);
            const float4 v3 = ld_row4(s_idxB[j + 3], m4);
            acc.x += v0.x; acc.y += v0.y; acc.z += v0.z; acc.w += v0.w;
            acc.x += v1.x; acc.y += v1.y; acc.z += v1.z; acc.w += v1.w;
            acc.x += v2.x; acc.y += v2.y; acc.z += v2.z; acc.w += v2.w;
            acc.x += v3.x; acc.y += v3.y; acc.z += v3.z; acc.w += v3.w;
        }
        for (; j < k1; j++) {
            const float4 v = ld_row4(s_idxB[j], m4);
            acc.x += v.x; acc.y += v.y; acc.z += v.z; acc.w += v.w;
        }
        reinterpret_cast<float4*>(&s_pB[grp * 256])[m4] = acc;
    }
    __syncthreads();

    // ---- combine quarters (fixed g-order) + bias + stm blend + clip ----
    {
        const float bias = ft_b[tid];
        const float accW = bias + s_pW[tid] + s_pW[256 + tid]
                                + s_pW[512 + tid] + s_pW[768 + tid];
        const float accB = bias + s_pB[tid] + s_pB[256 + tid]
                                + s_pB[512 + tid] + s_pB[768 + tid];
        const float s = stm[b];
        s_h[tid]       = clamp01(s * accW + (1.0f - s) * accB);
        s_h[256 + tid] = clamp01(s * accB + (1.0f - s) * accW);
    }
    __syncthreads();

    // L1: 512 -> 32, warp-per-output (4 outputs per warp), coalesced rows.
    {
        const float4* hv = reinterpret_cast<const float4*>(s_h);
        #pragma unroll
        for (int r = 0; r < 4; r++) {
            const int n = wid * 4 + r;
            const float4* wr = reinterpret_cast<const float4*>(l1_w + n * 512);
            float p = 0.0f;
            #pragma unroll
            for (int i = 0; i < 4; i++) {
                const float4 a = wr[i * 32 + lane];
                const float4 x = hv[i * 32 + lane];
                p += a.x * x.x;
                p += a.y * x.y;
                p += a.z * x.z;
                p += a.w * x.w;
            }
            p += __shfl_down_sync(0xffffffffu, p, 16);
            p += __shfl_down_sync(0xffffffffu, p, 8);
            p += __shfl_down_sync(0xffffffffu, p, 4);
            p += __shfl_down_sync(0xffffffffu, p, 2);
            p += __shfl_down_sync(0xffffffffu, p, 1);
            if (lane == 0) s_l2x[n] = clamp01(p + l1_b[n]);
        }
    }
    __syncthreads();

    // L2 (32->32) from padded smem, L3 (32->1). Warp 0 only.
    if (tid < 32) {
        float q = l2_b[tid];
        #pragma unroll
        for (int k = 0; k < 32; k++) q += s_l2w[tid * 33 + k] * s_l2x[k];
        const float l3x = clamp01(q);
        float t = l3x * l3_w[tid];
        #pragma unroll
        for (int off = 16; off > 0; off >>= 1)
            t += __shfl_down_sync(0xffffffffu, t, off);
        if (tid == 0) {
            const float ev = clamp01(t + l3_b[0]);
            out[b] = (ev - 0.5f) * 2.0f * 10000.0f;
        }
    }
}

// ---------------------------------------------------------------------------
// Launch
// ---------------------------------------------------------------------------
extern "C" void kernel_launch(void* const* d_in, const int* in_sizes, int n_in,
                              void* d_out, int out_size)
{
    const float* wf    = (const float*)d_in[0];
    const float* bfeat = (const float*)d_in[1];
    const float* stm   = (const float*)d_in[2];
    const float* ft_w  = (const float*)d_in[3];
    const float* ft_b  = (const float*)d_in[4];
    const float* l1_w  = (const float*)d_in[5];
    const float* l1_b  = (const float*)d_in[6];
    const float* l2_w  = (const float*)d_in[7];
    const float* l2_b  = (const float*)d_in[8];
    const float* l3_w  = (const float*)d_in[9];
    const float* l3_b  = (const float*)d_in[10];
    float* out = (float*)d_out;

    // 1) Fused scan (bitmap) + transpose in one grid
    scan_transpose_kernel<<<SCAN_CTAS + TR_CTAS, 256>>>(wf, bfeat, ft_w);

    // 2) Decode + float4 gather + MLP tail, one CTA per position
    gather_mlp_kernel<<<NB, 256>>>(stm, ft_b, l1_w, l1_b, l2_w, l2_b,
                                   l3_w, l3_b, out);
}

// round 13
// speedup vs baseline: 1.1716x; 1.0621x over previous
#include <cuda_runtime.h>
#include <cstdint>

#define NF       40960
#define MDIM     256
#define NB       2048
#define ROWS     (2*NB)          // 4096 feature rows (white then black)
#define CHUNK_V4 1280            // float4s per warp chunk (NF/4/8)
#define NSEG     8               // segments per row (one per eighth)
#define SEG_CAP  32              // capacity per segment (lambda=4, validated)

#define SCAN_CTAS 4096           // 8 warps per CTA, warp per (row, eighth)
#define TR_X      (NF/32)        // 1280
#define TR_Y      (MDIM/32)      // 8
#define TR_CTAS   (TR_X*TR_Y)    // 10240

// Transposed feature-transformer weights: ft_wT[f][m], 40960 x 256 fp32 = 41.9 MB
__device__ float g_ftwT[NF * MDIM];
// Per-(row, eighth) compact feature-index lists + counts (deterministic order)
__device__ int g_list[ROWS * NSEG * SEG_CAP];   // 4 MB
__device__ int g_scnt[ROWS * NSEG];

// ---------------------------------------------------------------------------
// Kernel 1: fused [streaming scan -> segment lists] + [ft_w transpose].
// Scan warp per (row, eighth). Per 4KB batch: lane-local nonzero mask, ONE
// ballot, parallel warp exclusive scan of popc(mask), each lane writes its
// own features at deterministic slots (batch, lane, bit). No serial bit-walk.
// ---------------------------------------------------------------------------
__global__ __launch_bounds__(256) void scan_transpose_kernel(
    const float* __restrict__ wf,
    const float* __restrict__ bfeat,
    const float* __restrict__ ft_w)
{
    __shared__ float tile[32][33];

    if (blockIdx.x < SCAN_CTAS) {
        const int gw     = (blockIdx.x << 3) | (threadIdx.x >> 5);
        const int lane   = threadIdx.x & 31;
        const int row    = gw >> 3;
        const int eighth = gw & 7;

        const float* rowp = (row < NB) ? (wf + (size_t)row * NF)
                                       : (bfeat + (size_t)(row - NB) * NF);
        const uint4* p = reinterpret_cast<const uint4*>(rowp) + eighth * CHUNK_V4;
        int* list = g_list + ((size_t)row * NSEG + eighth) * SEG_CAP;

        int base = 0;   // warp-uniform count so far

        #pragma unroll
        for (int t = 0; t < 5; t++) {
            unsigned mask = 0u;
            #pragma unroll
            for (int g = 0; g < 2; g++) {
                uint4 v0 = __ldcs(&p[t * 256 + (g * 4 + 0) * 32 + lane]);
                uint4 v1 = __ldcs(&p[t * 256 + (g * 4 + 1) * 32 + lane]);
                uint4 v2 = __ldcs(&p[t * 256 + (g * 4 + 2) * 32 + lane]);
                uint4 v3 = __ldcs(&p[t * 256 + (g * 4 + 3) * 32 + lane]);
                const int s = g * 16;
                if (v0.x) mask |= 1u << (s + 0);  if (v0.y) mask |= 1u << (s + 1);
                if (v0.z) mask |= 1u << (s + 2);  if (v0.w) mask |= 1u << (s + 3);
                if (v1.x) mask |= 1u << (s + 4);  if (v1.y) mask |= 1u << (s + 5);
                if (v1.z) mask |= 1u << (s + 6);  if (v1.w) mask |= 1u << (s + 7);
                if (v2.x) mask |= 1u << (s + 8);  if (v2.y) mask |= 1u << (s + 9);
                if (v2.z) mask |= 1u << (s + 10); if (v2.w) mask |= 1u << (s + 11);
                if (v3.x) mask |= 1u << (s + 12); if (v3.y) mask |= 1u << (s + 13);
                if (v3.z) mask |= 1u << (s + 14); if (v3.w) mask |= 1u << (s + 15);
            }

            const unsigned bal = __ballot_sync(0xffffffffu, mask != 0u);
            if (bal) {
                const int c = __popc(mask);
                // parallel exclusive scan of c over the warp
                int inc = c;
                #pragma unroll
                for (int d = 1; d < 32; d <<= 1) {
                    const int n = __shfl_up_sync(0xffffffffu, inc, d);
                    if (lane >= d) inc += n;
                }
                const int exc   = inc - c;
                const int total = __shfl_sync(0xffffffffu, inc, 31);
                // lane writes its own features (deterministic slots)
                unsigned mm = mask;
                int k = 0;
                while (mm) {
                    const int bb = __ffs(mm) - 1;
                    mm &= mm - 1u;
                    const int f = eighth * 5120
                                + (t * 256 + (bb >> 2) * 32 + lane) * 4 + (bb & 3);
                    const int slot = base + exc + k;
                    if (slot < SEG_CAP) list[slot] = f;
                    k++;
                }
                base += total;
            }
        }
        if (lane == 0)
            g_scnt[row * NSEG + eighth] = (base < SEG_CAP) ? base : SEG_CAP;
    } else {
        const int tb = blockIdx.x - SCAN_CTAS;
        const int f0 = (tb % TR_X) * 32;
        const int m0 = (tb / TR_X) * 32;
        const int t  = threadIdx.x;
        {
            const int m = t >> 3;
            const int q = t & 7;
            const float4 v = *reinterpret_cast<const float4*>(
                ft_w + (size_t)(m0 + m) * NF + f0 + q * 4);
            tile[m][q * 4 + 0] = v.x;
            tile[m][q * 4 + 1] = v.y;
            tile[m][q * 4 + 2] = v.z;
            tile[m][q * 4 + 3] = v.w;
        }
        __syncthreads();
        {
            const int f  = t >> 3;
            const int m4 = t & 7;
            float4 v;
            v.x = tile[m4 * 4 + 0][f];
            v.y = tile[m4 * 4 + 1][f];
            v.z = tile[m4 * 4 + 2][f];
            v.w = tile[m4 * 4 + 3][f];
            *reinterpret_cast<float4*>(
                g_ftwT + (size_t)(f0 + f) * MDIM + m0 + m4 * 4) = v;
        }
    }
}

// ---------------------------------------------------------------------------
// Kernel 2: list compaction + float4 gather + MLP tail. 256 threads/position.
// ---------------------------------------------------------------------------
__device__ __forceinline__ float clamp01(float x) {
    return fminf(fmaxf(x, 0.0f), 1.0f);
}

__device__ __forceinline__ float4 ld_row4(int f, int m4) {
    return reinterpret_cast<const float4*>(g_ftwT + (size_t)f * MDIM)[m4];
}

__global__ __launch_bounds__(256) void gather_mlp_kernel(
    const float* __restrict__ stm,
    const float* __restrict__ ft_b,
    const float* __restrict__ l1_w,
    const float* __restrict__ l1_b,
    const float* __restrict__ l2_w,
    const float* __restrict__ l2_b,
    const float* __restrict__ l3_w,
    const float* __restrict__ l3_b,
    float* __restrict__ out)
{
    const int b    = blockIdx.x;
    const int tid  = threadIdx.x;
    const int lane = tid & 31;
    const int wid  = tid >> 5;
    const int m4   = tid & 63;     // float4 column group
    const int grp  = tid >> 6;     // quarter of the index list

    __shared__ __align__(16) float s_h[512];
    __shared__ __align__(16) float s_pW[4 * 256];
    __shared__ __align__(16) float s_pB[4 * 256];
    __shared__ __align__(16) int   s_idxW[NSEG * SEG_CAP];  // 256
    __shared__ __align__(16) int   s_idxB[NSEG * SEG_CAP];
    __shared__ float s_l2w[32 * 33];
    __shared__ float s_l2x[32];
    __shared__ int   s_cntW[8], s_cntB[8];
    __shared__ int   s_nW, s_nB;

    // stage l2_w into padded smem
    #pragma unroll
    for (int i = tid; i < 1024; i += 256)
        s_l2w[(i >> 5) * 33 + (i & 31)] = l2_w[i];

    // segment counts
    if (tid < 8)       s_cntW[tid]     = g_scnt[b * NSEG + tid];
    else if (tid < 16) s_cntB[tid - 8] = g_scnt[(NB + b) * NSEG + (tid - 8)];
    __syncthreads();

    // compact the 8 segments into dense lists (deterministic segment order)
    {
        const int seg  = tid >> 5;
        const int slot = tid & 31;
        const int cW = s_cntW[seg];
        const int cB = s_cntB[seg];
        int offW = 0, offB = 0;
        #pragma unroll
        for (int i = 0; i < 7; i++) {
            if (i < seg) { offW += s_cntW[i]; offB += s_cntB[i]; }
        }
        const int fW = g_list[((size_t)b * NSEG + seg) * SEG_CAP + slot];
        const int fB = g_list[((size_t)(NB + b) * NSEG + seg) * SEG_CAP + slot];
        __syncthreads();  // all reads of s_cnt done before nW/nB writes? (no overwrite; safe)
        if (slot < cW) s_idxW[offW + slot] = fW;
        if (slot < cB) s_idxB[offB + slot] = fB;
        if (tid == 255) {            // seg=7: off covers segs 0..6
            s_nW = offW + cW;
            s_nB = offB + cB;
        }
    }
    __syncthreads();

    // ---- float4 gather over this thread's quarter of each list ----
    {
        const int nW = s_nW;
        const int j0 = (nW * grp) >> 2;
        const int j1 = (nW * (grp + 1)) >> 2;
        float4 acc = make_float4(0.f, 0.f, 0.f, 0.f);
        int j = j0;
        for (; j + 4 <= j1; j += 4) {
            const float4 v0 = ld_row4(s_idxW[j + 0], m4);
            const float4 v1 = ld_row4(s_idxW[j + 1], m4);
            const float4 v2 = ld_row4(s_idxW[j + 2], m4);
            const float4 v3 = ld_row4(s_idxW[j + 3], m4);
            acc.x += v0.x; acc.y += v0.y; acc.z += v0.z; acc.w += v0.w;
            acc.x += v1.x; acc.y += v1.y; acc.z += v1.z; acc.w += v1.w;
            acc.x += v2.x; acc.y += v2.y; acc.z += v2.z; acc.w += v2.w;
            acc.x += v3.x; acc.y += v3.y; acc.z += v3.z; acc.w += v3.w;
        }
        for (; j < j1; j++) {
            const float4 v = ld_row4(s_idxW[j], m4);
            acc.x += v.x; acc.y += v.y; acc.z += v.z; acc.w += v.w;
        }
        reinterpret_cast<float4*>(&s_pW[grp * 256])[m4] = acc;

        const int nB = s_nB;
        const int k0 = (nB * grp) >> 2;
        const int k1 = (nB * (grp + 1)) >> 2;
        acc = make_float4(0.f, 0.f, 0.f, 0.f);
        j = k0;
        for (; j + 4 <= k1; j += 4) {
            const float4 v0 = ld_row4(s_idxB[j + 0], m4);
            const float4 v1 = ld_row4(s_idxB[j + 1], m4);
            const float4 v2 = ld_row4(s_idxB[j + 2], m4);
            const float4 v3 = ld_row4(s_idxB[j + 3], m4);
            acc.x += v0.x; acc.y += v0.y; acc.z += v0.z; acc.w += v0.w;
            acc.x += v1.x; acc.y += v1.y; acc.z += v1.z; acc.w += v1.w;
            acc.x += v2.x; acc.y += v2.y; acc.z += v2.z; acc.w += v2.w;
            acc.x += v3.x; acc.y += v3.y; acc.z += v3.z; acc.w += v3.w;
        }
        for (; j < k1; j++) {
            const float4 v = ld_row4(s_idxB[j], m4);
            acc.x += v.x; acc.y += v.y; acc.z += v.z; acc.w += v.w;
        }
        reinterpret_cast<float4*>(&s_pB[grp * 256])[m4] = acc;
    }
    __syncthreads();

    // ---- combine quarters (fixed g-order) + bias + stm blend + clip ----
    {
        const float bias = ft_b[tid];
        const float accW = bias + s_pW[tid] + s_pW[256 + tid]
                                + s_pW[512 + tid] + s_pW[768 + tid];
        const float accB = bias + s_pB[tid] + s_pB[256 + tid]
                                + s_pB[512 + tid] + s_pB[768 + tid];
        const float s = stm[b];
        s_h[tid]       = clamp01(s * accW + (1.0f - s) * accB);
        s_h[256 + tid] = clamp01(s * accB + (1.0f - s) * accW);
    }
    __syncthreads();

    // L1: 512 -> 32, warp-per-output (4 outputs per warp), coalesced rows.
    {
        const float4* hv = reinterpret_cast<const float4*>(s_h);
        #pragma unroll
        for (int r = 0; r < 4; r++) {
            const int n = wid * 4 + r;
            const float4* wr = reinterpret_cast<const float4*>(l1_w + n * 512);
            float p = 0.0f;
            #pragma unroll
            for (int i = 0; i < 4; i++) {
                const float4 a = wr[i * 32 + lane];
                const float4 x = hv[i * 32 + lane];
                p += a.x * x.x;
                p += a.y * x.y;
                p += a.z * x.z;
                p += a.w * x.w;
            }
            p += __shfl_down_sync(0xffffffffu, p, 16);
            p += __shfl_down_sync(0xffffffffu, p, 8);
            p += __shfl_down_sync(0xffffffffu, p, 4);
            p += __shfl_down_sync(0xffffffffu, p, 2);
            p += __shfl_down_sync(0xffffffffu, p, 1);
            if (lane == 0) s_l2x[n] = clamp01(p + l1_b[n]);
        }
    }
    __syncthreads();

    // L2 (32->32) from padded smem, L3 (32->1). Warp 0 only.
    if (tid < 32) {
        float q = l2_b[tid];
        #pragma unroll
        for (int k = 0; k < 32; k++) q += s_l2w[tid * 33 + k] * s_l2x[k];
        const float l3x = clamp01(q);
        float t = l3x * l3_w[tid];
        #pragma unroll
        for (int off = 16; off > 0; off >>= 1)
            t += __shfl_down_sync(0xffffffffu, t, off);
        if (tid == 0) {
            const float ev = clamp01(t + l3_b[0]);
            out[b] = (ev - 0.5f) * 2.0f * 10000.0f;
        }
    }
}

// ---------------------------------------------------------------------------
// Launch
// ---------------------------------------------------------------------------
extern "C" void kernel_launch(void* const* d_in, const int* in_sizes, int n_in,
                              void* d_out, int out_size)
{
    const float* wf    = (const float*)d_in[0];
    const float* bfeat = (const float*)d_in[1];
    const float* stm   = (const float*)d_in[2];
    const float* ft_w  = (const float*)d_in[3];
    const float* ft_b  = (const float*)d_in[4];
    const float* l1_w  = (const float*)d_in[5];
    const float* l1_b  = (const float*)d_in[6];
    const float* l2_w  = (const float*)d_in[7];
    const float* l2_b  = (const float*)d_in[8];
    const float* l3_w  = (const float*)d_in[9];
    const float* l3_b  = (const float*)d_in[10];
    float* out = (float*)d_out;

    // 1) Fused scan (segment lists) + transpose in one grid
    scan_transpose_kernel<<<SCAN_CTAS + TR_CTAS, 256>>>(wf, bfeat, ft_w);

    // 2) Compaction + float4 gather + MLP tail, one CTA per position
    gather_mlp_kernel<<<NB, 256>>>(stm, ft_b, l1_w, l1_b, l2_w, l2_b,
                                   l3_w, l3_b, out);
}

// round 14
// speedup vs baseline: 1.2532x; 1.0696x over previous
#include <cuda_runtime.h>
#include <cuda_fp16.h>
#include <cstdint>

#define NF       40960
#define MDIM     256
#define NB       2048
#define ROWS     (2*NB)          // 4096 feature rows (white then black)
#define CHUNK_V4 1280            // float4s per warp chunk (NF/4/8)
#define NSEG     8               // segments per row (one per eighth)
#define SEG_CAP  32              // capacity per segment

#define SCAN_CTAS 4096           // 8 warps per CTA, warp per (row, eighth)
#define TR_X      (NF/32)        // 1280
#define TR_Y      (MDIM/32)      // 8
#define TR_CTAS   (TR_X*TR_Y)    // 10240

// Transposed feature-transformer weights in fp16: ft_wT[f][m], 21 MB.
// Accumulation stays fp32; only table storage is half (err ~1e-4 << 1e-3).
__device__ __half g_ftwT[NF * MDIM];
// Per-(row, eighth) compact feature-index lists + counts (deterministic order)
__device__ int g_list[ROWS * NSEG * SEG_CAP];   // 4 MB
__device__ int g_scnt[ROWS * NSEG];

// ---------------------------------------------------------------------------
// Kernel 1: fused [streaming scan -> segment lists] + [ft_w transpose->fp16].
// ---------------------------------------------------------------------------
__global__ __launch_bounds__(256) void scan_transpose_kernel(
    const float* __restrict__ wf,
    const float* __restrict__ bfeat,
    const float* __restrict__ ft_w)
{
    __shared__ float tile[32][33];

    if (blockIdx.x < SCAN_CTAS) {
        const int gw     = (blockIdx.x << 3) | (threadIdx.x >> 5);
        const int lane   = threadIdx.x & 31;
        const int row    = gw >> 3;
        const int eighth = gw & 7;

        const float* rowp = (row < NB) ? (wf + (size_t)row * NF)
                                       : (bfeat + (size_t)(row - NB) * NF);
        const uint4* p = reinterpret_cast<const uint4*>(rowp) + eighth * CHUNK_V4;
        int* list = g_list + ((size_t)row * NSEG + eighth) * SEG_CAP;

        int base = 0;   // warp-uniform count so far

        #pragma unroll
        for (int t = 0; t < 5; t++) {
            unsigned mask = 0u;
            #pragma unroll
            for (int g = 0; g < 2; g++) {
                uint4 v0 = __ldcs(&p[t * 256 + (g * 4 + 0) * 32 + lane]);
                uint4 v1 = __ldcs(&p[t * 256 + (g * 4 + 1) * 32 + lane]);
                uint4 v2 = __ldcs(&p[t * 256 + (g * 4 + 2) * 32 + lane]);
                uint4 v3 = __ldcs(&p[t * 256 + (g * 4 + 3) * 32 + lane]);
                const int s = g * 16;
                if (v0.x) mask |= 1u << (s + 0);  if (v0.y) mask |= 1u << (s + 1);
                if (v0.z) mask |= 1u << (s + 2);  if (v0.w) mask |= 1u << (s + 3);
                if (v1.x) mask |= 1u << (s + 4);  if (v1.y) mask |= 1u << (s + 5);
                if (v1.z) mask |= 1u << (s + 6);  if (v1.w) mask |= 1u << (s + 7);
                if (v2.x) mask |= 1u << (s + 8);  if (v2.y) mask |= 1u << (s + 9);
                if (v2.z) mask |= 1u << (s + 10); if (v2.w) mask |= 1u << (s + 11);
                if (v3.x) mask |= 1u << (s + 12); if (v3.y) mask |= 1u << (s + 13);
                if (v3.z) mask |= 1u << (s + 14); if (v3.w) mask |= 1u << (s + 15);
            }

            const unsigned bal = __ballot_sync(0xffffffffu, mask != 0u);
            if (bal) {
                const int c = __popc(mask);
                int inc = c;
                #pragma unroll
                for (int d = 1; d < 32; d <<= 1) {
                    const int n = __shfl_up_sync(0xffffffffu, inc, d);
                    if (lane >= d) inc += n;
                }
                const int exc   = inc - c;
                const int total = __shfl_sync(0xffffffffu, inc, 31);
                unsigned mm = mask;
                int k = 0;
                while (mm) {
                    const int bb = __ffs(mm) - 1;
                    mm &= mm - 1u;
                    const int f = eighth * 5120
                                + (t * 256 + (bb >> 2) * 32 + lane) * 4 + (bb & 3);
                    const int slot = base + exc + k;
                    if (slot < SEG_CAP) list[slot] = f;
                    k++;
                }
                base += total;
            }
        }
        if (lane == 0)
            g_scnt[row * NSEG + eighth] = (base < SEG_CAP) ? base : SEG_CAP;
    } else {
        const int tb = blockIdx.x - SCAN_CTAS;
        const int f0 = (tb % TR_X) * 32;
        const int m0 = (tb / TR_X) * 32;
        const int t  = threadIdx.x;
        {
            const int m = t >> 3;
            const int q = t & 7;
            const float4 v = *reinterpret_cast<const float4*>(
                ft_w + (size_t)(m0 + m) * NF + f0 + q * 4);
            tile[m][q * 4 + 0] = v.x;
            tile[m][q * 4 + 1] = v.y;
            tile[m][q * 4 + 2] = v.z;
            tile[m][q * 4 + 3] = v.w;
        }
        __syncthreads();
        {
            const int f  = t >> 3;
            const int m4 = t & 7;
            float4 v;
            v.x = tile[m4 * 4 + 0][f];
            v.y = tile[m4 * 4 + 1][f];
            v.z = tile[m4 * 4 + 2][f];
            v.w = tile[m4 * 4 + 3][f];
            union { __half2 h[2]; uint2 u; } cv;
            cv.h[0] = __floats2half2_rn(v.x, v.y);
            cv.h[1] = __floats2half2_rn(v.z, v.w);
            *reinterpret_cast<uint2*>(
                g_ftwT + (size_t)(f0 + f) * MDIM + m0 + m4 * 4) = cv.u;
        }
    }
}

// ---------------------------------------------------------------------------
// Kernel 2: list compaction + fp16 gather (fp32 accumulate) + MLP tail.
// ---------------------------------------------------------------------------
__device__ __forceinline__ float clamp01(float x) {
    return fminf(fmaxf(x, 0.0f), 1.0f);
}

__device__ __forceinline__ float4 ld_row4h(int f, int m4) {
    const uint2 u = reinterpret_cast<const uint2*>(g_ftwT + (size_t)f * MDIM)[m4];
    const __half2 h0 = *reinterpret_cast<const __half2*>(&u.x);
    const __half2 h1 = *reinterpret_cast<const __half2*>(&u.y);
    const float2 f0 = __half22float2(h0);
    const float2 f1 = __half22float2(h1);
    return make_float4(f0.x, f0.y, f1.x, f1.y);
}

__global__ __launch_bounds__(256) void gather_mlp_kernel(
    const float* __restrict__ stm,
    const float* __restrict__ ft_b,
    const float* __restrict__ l1_w,
    const float* __restrict__ l1_b,
    const float* __restrict__ l2_w,
    const float* __restrict__ l2_b,
    const float* __restrict__ l3_w,
    const float* __restrict__ l3_b,
    float* __restrict__ out)
{
    const int b    = blockIdx.x;
    const int tid  = threadIdx.x;
    const int lane = tid & 31;
    const int wid  = tid >> 5;
    const int m4   = tid & 63;     // half2x2 column group (m = m4*4..m4*4+3)
    const int grp  = tid >> 6;     // quarter of the index list

    __shared__ __align__(16) float s_h[512];
    __shared__ __align__(16) float s_pW[4 * 256];
    __shared__ __align__(16) float s_pB[4 * 256];
    __shared__ __align__(16) int   s_idxW[NSEG * SEG_CAP];  // 256
    __shared__ __align__(16) int   s_idxB[NSEG * SEG_CAP];
    __shared__ float s_l2w[32 * 33];
    __shared__ float s_l2x[32];
    __shared__ int   s_cntW[8], s_cntB[8];
    __shared__ int   s_nW, s_nB;

    // stage l2_w into padded smem
    #pragma unroll
    for (int i = tid; i < 1024; i += 256)
        s_l2w[(i >> 5) * 33 + (i & 31)] = l2_w[i];

    // segment counts
    if (tid < 8)       s_cntW[tid]     = g_scnt[b * NSEG + tid];
    else if (tid < 16) s_cntB[tid - 8] = g_scnt[(NB + b) * NSEG + (tid - 8)];
    __syncthreads();

    // compact the 8 segments into dense lists (deterministic segment order)
    {
        const int seg  = tid >> 5;
        const int slot = tid & 31;
        const int cW = s_cntW[seg];
        const int cB = s_cntB[seg];
        int offW = 0, offB = 0;
        #pragma unroll
        for (int i = 0; i < 7; i++) {
            if (i < seg) { offW += s_cntW[i]; offB += s_cntB[i]; }
        }
        const int fW = g_list[((size_t)b * NSEG + seg) * SEG_CAP + slot];
        const int fB = g_list[((size_t)(NB + b) * NSEG + seg) * SEG_CAP + slot];
        __syncthreads();
        if (slot < cW) s_idxW[offW + slot] = fW;
        if (slot < cB) s_idxB[offB + slot] = fB;
        if (tid == 255) {
            s_nW = offW + cW;
            s_nB = offB + cB;
        }
    }
    __syncthreads();

    // ---- fp16 gather (fp32 accumulate) over this thread's quarter ----
    {
        const int nW = s_nW;
        const int j0 = (nW * grp) >> 2;
        const int j1 = (nW * (grp + 1)) >> 2;
        float4 acc = make_float4(0.f, 0.f, 0.f, 0.f);
        int j = j0;
        for (; j + 4 <= j1; j += 4) {
            const float4 v0 = ld_row4h(s_idxW[j + 0], m4);
            const float4 v1 = ld_row4h(s_idxW[j + 1], m4);
            const float4 v2 = ld_row4h(s_idxW[j + 2], m4);
            const float4 v3 = ld_row4h(s_idxW[j + 3], m4);
            acc.x += v0.x; acc.y += v0.y; acc.z += v0.z; acc.w += v0.w;
            acc.x += v1.x; acc.y += v1.y; acc.z += v1.z; acc.w += v1.w;
            acc.x += v2.x; acc.y += v2.y; acc.z += v2.z; acc.w += v2.w;
            acc.x += v3.x; acc.y += v3.y; acc.z += v3.z; acc.w += v3.w;
        }
        for (; j < j1; j++) {
            const float4 v = ld_row4h(s_idxW[j], m4);
            acc.x += v.x; acc.y += v.y; acc.z += v.z; acc.w += v.w;
        }
        reinterpret_cast<float4*>(&s_pW[grp * 256])[m4] = acc;

        const int nB = s_nB;
        const int k0 = (nB * grp) >> 2;
        const int k1 = (nB * (grp + 1)) >> 2;
        acc = make_float4(0.f, 0.f, 0.f, 0.f);
        j = k0;
        for (; j + 4 <= k1; j += 4) {
            const float4 v0 = ld_row4h(s_idxB[j + 0], m4);
            const float4 v1 = ld_row4h(s_idxB[j + 1], m4);
            const float4 v2 = ld_row4h(s_idxB[j + 2], m4);
            const float4 v3 = ld_row4h(s_idxB[j + 3], m4);
            acc.x += v0.x; acc.y += v0.y; acc.z += v0.z; acc.w += v0.w;
            acc.x += v1.x; acc.y += v1.y; acc.z += v1.z; acc.w += v1.w;
            acc.x += v2.x; acc.y += v2.y; acc.z += v2.z; acc.w += v2.w;
            acc.x += v3.x; acc.y += v3.y; acc.z += v3.z; acc.w += v3.w;
        }
        for (; j < k1; j++) {
            const float4 v = ld_row4h(s_idxB[j], m4);
            acc.x += v.x; acc.y += v.y; acc.z += v.z; acc.w += v.w;
        }
        reinterpret_cast<float4*>(&s_pB[grp * 256])[m4] = acc;
    }
    __syncthreads();

    // ---- combine quarters (fixed g-order) + bias + stm blend + clip ----
    {
        const float bias = ft_b[tid];
        const float accW = bias + s_pW[tid] + s_pW[256 + tid]
                                + s_pW[512 + tid] + s_pW[768 + tid];
        const float accB = bias + s_pB[tid] + s_pB[256 + tid]
                                + s_pB[512 + tid] + s_pB[768 + tid];
        const float s = stm[b];
        s_h[tid]       = clamp01(s * accW + (1.0f - s) * accB);
        s_h[256 + tid] = clamp01(s * accB + (1.0f - s) * accW);
    }
    __syncthreads();

    // L1: 512 -> 32, warp-per-output (4 outputs per warp), coalesced rows.
    {
        const float4* hv = reinterpret_cast<const float4*>(s_h);
        #pragma unroll
        for (int r = 0; r < 4; r++) {
            const int n = wid * 4 + r;
            const float4* wr = reinterpret_cast<const float4*>(l1_w + n * 512);
            float p = 0.0f;
            #pragma unroll
            for (int i = 0; i < 4; i++) {
                const float4 a = wr[i * 32 + lane];
                const float4 x = hv[i * 32 + lane];
                p += a.x * x.x;
                p += a.y * x.y;
                p += a.z * x.z;
                p += a.w * x.w;
            }
            p += __shfl_down_sync(0xffffffffu, p, 16);
            p += __shfl_down_sync(0xffffffffu, p, 8);
            p += __shfl_down_sync(0xffffffffu, p, 4);
            p += __shfl_down_sync(0xffffffffu, p, 2);
            p += __shfl_down_sync(0xffffffffu, p, 1);
            if (lane == 0) s_l2x[n] = clamp01(p + l1_b[n]);
        }
    }
    __syncthreads();

    // L2 (32->32) from padded smem, L3 (32->1). Warp 0 only.
    if (tid < 32) {
        float q = l2_b[tid];
        #pragma unroll
        for (int k = 0; k < 32; k++) q += s_l2w[tid * 33 + k] * s_l2x[k];
        const float l3x = clamp01(q);
        float t = l3x * l3_w[tid];
        #pragma unroll
        for (int off = 16; off > 0; off >>= 1)
            t += __shfl_down_sync(0xffffffffu, t, off);
        if (tid == 0) {
            const float ev = clamp01(t + l3_b[0]);
            out[b] = (ev - 0.5f) * 2.0f * 10000.0f;
        }
    }
}

// ---------------------------------------------------------------------------
// Launch
// ---------------------------------------------------------------------------
extern "C" void kernel_launch(void* const* d_in, const int* in_sizes, int n_in,
                              void* d_out, int out_size)
{
    const float* wf    = (const float*)d_in[0];
    const float* bfeat = (const float*)d_in[1];
    const float* stm   = (const float*)d_in[2];
    const float* ft_w  = (const float*)d_in[3];
    const float* ft_b  = (const float*)d_in[4];
    const float* l1_w  = (const float*)d_in[5];
    const float* l1_b  = (const float*)d_in[6];
    const float* l2_w  = (const float*)d_in[7];
    const float* l2_b  = (const float*)d_in[8];
    const float* l3_w  = (const float*)d_in[9];
    const float* l3_b  = (const float*)d_in[10];
    float* out = (float*)d_out;

    // 1) Fused scan (segment lists) + fp16 transpose in one grid
    scan_transpose_kernel<<<SCAN_CTAS + TR_CTAS, 256>>>(wf, bfeat, ft_w);

    // 2) Compaction + fp16 gather + MLP tail, one CTA per position
    gather_mlp_kernel<<<NB, 256>>>(stm, ft_b, l1_w, l1_b, l2_w, l2_b,
                                   l3_w, l3_b, out);
}